// round 17
// baseline (speedup 1.0000x reference)
#include <cuda_runtime.h>
#include <cstdint>

#define MAXN 100000
#define MAXE 2000000
#define MAXNB 128   // max 1024-blocks covering N

// ---------------- scratch (device globals) ------------------------------------
__device__ __align__(16) float g_x8[MAXN * 8];             // x padded to 32B/node
__device__ __align__(16) float g_as1[MAXN * 4];
__device__ __align__(16) float g_ad1[MAXN * 4];
__device__ __align__(16) float g_acc1[MAXN * 32];          // [n][h][8]: sum(e*x0..5), den, pad
__device__ __align__(16) float g_h2[MAXN * 64];            // elu(out1) @ W2
__device__ __align__(16) float g_as2[MAXN];
__device__ __align__(16) float g_ad2[MAXN];
__device__ __align__(16) float g_hf[MAXN * 64];            // layer-2 output (post elu)
__device__ __align__(16) int   g_didx[MAXN];
__device__ __align__(16) int   g_src[MAXE];
__device__ __align__(16) int   g_dst[MAXE];
__device__ __align__(16) int   g_csr[MAXE];                // src ids grouped by dst
__device__ __align__(16) int   g_deg[MAXN];
__device__ __align__(16) int   g_off[MAXN];
__device__ __align__(16) int   g_wr[MAXN];
__device__ unsigned long long g_lbk[MAXNB];                // lookback state
__device__ int g_is64;

#define LBK_A (1ull << 62)
#define LBK_P (1ull << 63)
#define LBK_V ((1ull << 58) - 1ull)

// ---------------- helpers ----------------------------------------------------
__device__ __forceinline__ float lrelu(float v) { return v > 0.f ? v : 0.2f * v; }
__device__ __forceinline__ float eluf(float v)  { return v > 0.f ? v : expm1f(v); }
__device__ __forceinline__ void ffma2(unsigned long long& acc,
                                      unsigned long long a, unsigned long long b) {
    asm("fma.rn.f32x2 %0, %1, %2, %0;" : "+l"(acc) : "l"(a), "l"(b));
}

// ---------------- KZ: zero deg/didx/lookback, + dtype probe -------------------
__global__ void kz_zero(const long long* __restrict__ ei, int N) {
    int n = blockIdx.x * blockDim.x + threadIdx.x;
    if (n < N) { g_deg[n] = 0; g_didx[n] = 0; }
    if (blockIdx.x == 0 && threadIdx.x < MAXNB) g_lbk[threadIdx.x] = 0ull;
    if (blockIdx.x == 0 && threadIdx.x == 0) {
        bool ok = true;
        #pragma unroll
        for (int i = 0; i < 16; i++) {
            long long v = ei[i];
            if (v < 0 || v >= (long long)N) { ok = false; break; }
        }
        g_is64 = ok ? 1 : 0;
    }
}

// ---------------- KC: decode edge list + histogram ----------------------------
__global__ void kc_cvt(const void* __restrict__ ei, int E, int N) {
    int e = blockIdx.x * blockDim.x + threadIdx.x;
    if (e >= E) return;
    int s, d;
    if (g_is64) {
        const long long* p = (const long long*)ei;
        s = (int)p[e]; d = (int)p[e + E];
    } else {
        const int* p = (const int*)ei;
        s = p[e]; d = p[e + E];
    }
    if ((unsigned)s >= (unsigned)N) s = 0;
    if ((unsigned)d >= (unsigned)N) d = 0;
    g_src[e] = s;
    g_dst[e] = d;
    atomicAdd(&g_deg[d], 1);
}

// ---------------- KSCAN: single-pass packed lookback scan ---------------------
// Scans (deg, drone_flag) jointly: value = (deg << 20) | flag. Produces CSR
// offsets AND the stable drone-index compaction in ONE kernel.
__global__ void kscan(const float* __restrict__ x, int N) {
    int b = blockIdx.x, t = threadIdx.x, n = b * 1024 + t;
    int l = t & 31, w = t >> 5;
    int deg = (n < N) ? g_deg[n] : 0;
    int fl  = (n < N) && (x[n * 6 + 5] == 1.0f);
    unsigned long long v = ((unsigned long long)deg << 20) | (unsigned)fl;
    unsigned long long s = v;
    #pragma unroll
    for (int o = 1; o < 32; o <<= 1) {
        unsigned long long u = __shfl_up_sync(0xffffffffu, s, o);
        if (l >= o) s += u;
    }
    __shared__ unsigned long long ws[32];
    __shared__ unsigned long long sbase;
    if (l == 31) ws[w] = s;
    __syncthreads();
    if (w == 0) {
        unsigned long long x2 = ws[l];
        #pragma unroll
        for (int o = 1; o < 32; o <<= 1) {
            unsigned long long u = __shfl_up_sync(0xffffffffu, x2, o);
            if (l >= o) x2 += u;
        }
        ws[l] = x2;
    }
    __syncthreads();
    unsigned long long incl  = s + (w ? ws[w - 1] : 0ull);
    unsigned long long total = ws[31];
    if (t == 0) {
        if (b == 0) {
            atomicExch(&g_lbk[0], LBK_P | total);
            sbase = 0ull;
        } else {
            atomicExch(&g_lbk[b], LBK_A | total);
            unsigned long long run = 0ull;
            int j = b - 1;
            while (true) {
                unsigned long long sv = atomicAdd(&g_lbk[j], 0ull);
                if (sv & LBK_P) { run += sv & LBK_V; break; }
                if (sv & LBK_A) { run += sv & LBK_V; j--; }
            }
            atomicExch(&g_lbk[b], LBK_P | (run + total));
            sbase = run;
        }
    }
    __syncthreads();
    unsigned long long excl = sbase + incl - v;
    if (n < N) {
        int doff = (int)(excl >> 20);
        g_off[n] = doff;
        g_wr[n]  = doff;
        if (fl) {
            int dp = (int)(excl & 0xFFFFFu);
            if (dp < MAXN) g_didx[dp] = n;
        }
    }
}

// ---------------- KSC: scatter srcs into CSR ----------------------------------
__global__ void kscat(int E) {
    int e = blockIdx.x * blockDim.x + threadIdx.x;
    if (e >= E) return;
    int d = g_dst[e];
    int pos = atomicAdd(&g_wr[d], 1);
    g_csr[pos] = g_src[e];
}

// ---------------- K1: per-block proj + node logits + x8 padding ---------------
__global__ void k1_logits1(const float* __restrict__ x,
                           const float* __restrict__ W1,
                           const float* __restrict__ att_s,
                           const float* __restrict__ att_d, int N) {
    __shared__ float sp[48];
    int t = threadIdx.x;
    if (t < 48) {
        int which = t / 24, r = t % 24, h = r / 6, i = r % 6;
        const float* att = which ? att_d : att_s;
        float s = 0.f;
        #pragma unroll 8
        for (int c = 0; c < 64; c++)
            s += W1[i * 256 + h * 64 + c] * att[h * 64 + c];
        sp[which * 24 + h * 6 + i] = s;
    }
    __syncthreads();
    int n = blockIdx.x * blockDim.x + t;
    if (n >= N) return;
    float xv[6];
    #pragma unroll
    for (int i = 0; i < 6; i++) xv[i] = x[n * 6 + i];
    *(float4*)&g_x8[n * 8]     = make_float4(xv[0], xv[1], xv[2], xv[3]);
    *(float4*)&g_x8[n * 8 + 4] = make_float4(xv[4], xv[5], 0.f, 0.f);
    float as[4], ad[4];
    #pragma unroll
    for (int h = 0; h < 4; h++) {
        float a = 0.f, d = 0.f;
        #pragma unroll
        for (int i = 0; i < 6; i++) {
            a += xv[i] * sp[h * 6 + i];
            d += xv[i] * sp[24 + h * 6 + i];
        }
        as[h] = a; ad[h] = d;
    }
    *(float4*)&g_as1[n * 4] = make_float4(as[0], as[1], as[2], as[3]);
    *(float4*)&g_ad1[n * 4] = make_float4(ad[0], ad[1], ad[2], ad[3]);
}

// ---------------- K4: layer-1 CSR aggregation (thread per dst, all 4 heads) ---
// exp without max-shift: mathematically identical softmax, values bounded.
__global__ void k4_csr(int N) {
    int d = blockIdx.x * blockDim.x + threadIdx.x;
    if (d >= N) return;
    float4 ad = *(const float4*)&g_ad1[d * 4];
    int off = g_off[d], deg = g_deg[d];
    float A[4][6], den[4];
    {   // self loop
        float4 av = *(const float4*)&g_as1[d * 4];
        float eh[4] = { __expf(lrelu(av.x + ad.x)), __expf(lrelu(av.y + ad.y)),
                        __expf(lrelu(av.z + ad.z)), __expf(lrelu(av.w + ad.w)) };
        float4 xa = *(const float4*)&g_x8[d * 8];
        float4 xb = *(const float4*)&g_x8[d * 8 + 4];
        float xs[6] = { xa.x, xa.y, xa.z, xa.w, xb.x, xb.y };
        #pragma unroll
        for (int h = 0; h < 4; h++) {
            den[h] = eh[h];
            #pragma unroll
            for (int i = 0; i < 6; i++) A[h][i] = eh[h] * xs[i];
        }
    }
    for (int i = 0; i < deg; i++) {
        int s = g_csr[off + i];
        float4 av = *(const float4*)&g_as1[s * 4];
        float eh[4] = { __expf(lrelu(av.x + ad.x)), __expf(lrelu(av.y + ad.y)),
                        __expf(lrelu(av.z + ad.z)), __expf(lrelu(av.w + ad.w)) };
        float4 xa = *(const float4*)&g_x8[s * 8];
        float4 xb = *(const float4*)&g_x8[s * 8 + 4];
        float xs[6] = { xa.x, xa.y, xa.z, xa.w, xb.x, xb.y };
        #pragma unroll
        for (int h = 0; h < 4; h++) {
            den[h] += eh[h];
            #pragma unroll
            for (int ii = 0; ii < 6; ii++) A[h][ii] += eh[h] * xs[ii];
        }
    }
    float* o = &g_acc1[d * 32];
    #pragma unroll
    for (int h = 0; h < 4; h++) {
        *(float4*)&o[h * 8]     = make_float4(A[h][0], A[h][1], A[h][2], A[h][3]);
        *(float4*)&o[h * 8 + 4] = make_float4(A[h][4], A[h][5], den[h], 0.f);
    }
}

// ---------------- K6F: fused  h2 = elu((acc@W1)/den + b1) @ W2 ----------------
__global__ void __launch_bounds__(256) k6_fused(
        const float* __restrict__ W1, const float* __restrict__ b1,
        const float* __restrict__ W2, int N) {
    __shared__ __align__(16) float sh[256 * 36];   // [k][node], pad 36
    __shared__ float sW1[1536];
    __shared__ float sb1[256];
    int t = threadIdx.x;
    int base = blockIdx.x * 32;
    for (int i = t; i < 1536; i += 256) sW1[i] = W1[i];
    sb1[t] = b1[t];
    __syncthreads();

    // ---- phase 1: build h1 tile in shared ----
    {
        int node = t & 31;
        int jb   = t >> 5;
        int n = base + node; if (n >= N) n = N - 1;
        const float* accp = &g_acc1[n * 32];
        #pragma unroll
        for (int h = 0; h < 4; h++) {
            float4 lo = *(const float4*)&accp[h * 8];
            float4 hi = *(const float4*)&accp[h * 8 + 4];
            float inv = 1.f / fmaxf(hi.z, 1e-16f);
            #pragma unroll
            for (int m = 0; m < 8; m++) {
                int j = h * 64 + jb + m * 8;
                float v = lo.x * sW1[j] + lo.y * sW1[256 + j] + lo.z * sW1[512 + j]
                        + lo.w * sW1[768 + j] + hi.x * sW1[1024 + j] + hi.y * sW1[1280 + j];
                v = v * inv + sb1[j];
                sh[j * 36 + node] = eluf(v);
            }
        }
    }
    __syncthreads();

    // ---- phase 2: GEMM tile @ W2, packed f32x2 (8 nodes x 1 col per thread) --
    {
        int j = t & 63, ng = t >> 6;
        unsigned long long A0 = 0ull, A1 = 0ull, A2 = 0ull, A3 = 0ull;
        const float* wp = W2 + j;
        #pragma unroll 4
        for (int k = 0; k < 256; k++) {
            ulonglong2 P = *(const ulonglong2*)&sh[k * 36 + ng * 8];
            ulonglong2 Q = *(const ulonglong2*)&sh[k * 36 + ng * 8 + 4];
            unsigned wu = __float_as_uint(__ldg(&wp[k * 64]));
            unsigned long long ww;
            asm("mov.b64 %0, {%1, %1};" : "=l"(ww) : "r"(wu));
            ffma2(A0, P.x, ww);
            ffma2(A1, P.y, ww);
            ffma2(A2, Q.x, ww);
            ffma2(A3, Q.y, ww);
        }
        int n0 = base + ng * 8;
        unsigned long long Ar[4] = { A0, A1, A2, A3 };
        #pragma unroll
        for (int m2 = 0; m2 < 4; m2++) {
            unsigned lo32, hi32;
            asm("mov.b64 {%0, %1}, %2;" : "=r"(lo32), "=r"(hi32) : "l"(Ar[m2]));
            int na = n0 + m2 * 2, nb2 = na + 1;
            if (na  < N) g_h2[na  * 64 + j] = __uint_as_float(lo32);
            if (nb2 < N) g_h2[nb2 * 64 + j] = __uint_as_float(hi32);
        }
    }
}

// ---------------- K6b: layer-2 logits (warp per node) -------------------------
__global__ void k6b_logits2(const float* __restrict__ att_s,
                            const float* __restrict__ att_d, int N) {
    int gt = blockIdx.x * blockDim.x + threadIdx.x;
    int n = gt >> 5, l = gt & 31;
    if (n >= N) return;
    float h0 = g_h2[n * 64 + l], h1v = g_h2[n * 64 + l + 32];
    float s = h0 * att_s[l] + h1v * att_s[l + 32];
    float d = h0 * att_d[l] + h1v * att_d[l + 32];
    #pragma unroll
    for (int o = 16; o; o >>= 1) {
        s += __shfl_down_sync(0xffffffffu, s, o);
        d += __shfl_down_sync(0xffffffffu, d, o);
    }
    if (l == 0) { g_as2[n] = s; g_ad2[n] = d; }
}

// ---------------- K9: layer-2 CSR aggregation, fully fused --------------------
__global__ void k9_csr(const float* __restrict__ b2, int N) {
    int gt = blockIdx.x * blockDim.x + threadIdx.x;
    int d = gt >> 5, l = gt & 31;
    if (d >= N) return;
    float add = g_ad2[d];
    int off = g_off[d], deg = g_deg[d];
    float eeS = __expf(lrelu(g_as2[d] + add));
    float2 hd = *(const float2*)&g_h2[d * 64 + l * 2];
    float ax = eeS * hd.x, ay = eeS * hd.y, den = eeS;
    int i = 0;
    for (; i + 4 <= deg; i += 4) {
        int s0 = g_csr[off + i],     s1 = g_csr[off + i + 1];
        int s2 = g_csr[off + i + 2], s3 = g_csr[off + i + 3];
        float e0 = __expf(lrelu(g_as2[s0] + add));
        float e1 = __expf(lrelu(g_as2[s1] + add));
        float e2 = __expf(lrelu(g_as2[s2] + add));
        float e3 = __expf(lrelu(g_as2[s3] + add));
        float2 h0 = *(const float2*)&g_h2[s0 * 64 + l * 2];
        float2 h1 = *(const float2*)&g_h2[s1 * 64 + l * 2];
        float2 h2v = *(const float2*)&g_h2[s2 * 64 + l * 2];
        float2 h3 = *(const float2*)&g_h2[s3 * 64 + l * 2];
        ax += e0 * h0.x + e1 * h1.x + e2 * h2v.x + e3 * h3.x;
        ay += e0 * h0.y + e1 * h1.y + e2 * h2v.y + e3 * h3.y;
        den += e0 + e1 + e2 + e3;
    }
    for (; i < deg; i++) {
        int s0 = g_csr[off + i];
        float e0 = __expf(lrelu(g_as2[s0] + add));
        float2 h0 = *(const float2*)&g_h2[s0 * 64 + l * 2];
        ax += e0 * h0.x; ay += e0 * h0.y; den += e0;
    }
    float inv = 1.f / fmaxf(den, 1e-16f);
    float v0 = ax * inv + b2[l * 2];
    float v1 = ay * inv + b2[l * 2 + 1];
    *(float2*)&g_hf[d * 64 + l * 2] = make_float2(eluf(v0), eluf(v1));
}

// ---------------- K12: drone MLP head, 16 drones/block, weights in shared -----
__global__ void k12_mlp(const float* __restrict__ fc1w, const float* __restrict__ fc1b,
                        const float* __restrict__ fc2w, const float* __restrict__ fc2b,
                        float* __restrict__ out, int nd) {
    __shared__ float sw1[4096];
    __shared__ float sb1v[64], sw2[128], sb2v[2];
    __shared__ float shv[64], szv[64];
    int t = threadIdx.x;  // 64
    for (int i = t; i < 4096; i += 64) sw1[i] = fc1w[i];
    sb1v[t] = fc1b[t];
    sw2[t] = fc2w[t];
    sw2[t + 64] = fc2w[t + 64];
    if (t < 2) sb2v[t] = fc2b[t];
    __syncthreads();
    int base = blockIdx.x * 16;
    for (int dd = 0; dd < 16; dd++) {
        int b = base + dd;
        if (b >= nd) break;
        int n = g_didx[b];
        shv[t] = g_hf[n * 64 + t];
        __syncthreads();
        float v = sb1v[t];
        #pragma unroll 8
        for (int k = 0; k < 64; k++) v += shv[k] * sw1[k * 64 + t];
        szv[t] = fmaxf(v, 0.f);
        __syncthreads();
        if (t < 2) {
            float o = sb2v[t];
            #pragma unroll 8
            for (int k = 0; k < 64; k++) o += szv[k] * sw2[k * 2 + t];
            out[b * 2 + t] = 2.f * tanhf(o);
        }
        __syncthreads();
    }
}

// ---------------- launch ------------------------------------------------------
static inline int cdiv(long long a, int b) { return (int)((a + b - 1) / b); }

extern "C" void kernel_launch(void* const* d_in, const int* in_sizes, int n_in,
                              void* d_out, int out_size) {
    // ---- size-based input identification (element counts) ----
    const void* p_ei = nullptr; const float* x = nullptr;
    const float *W1 = 0, *W2 = 0, *fc1w = 0, *fc2w = 0, *fc2b = 0;
    const float* s256[3] = {0, 0, 0}; int n256 = 0;
    const float* s64g[4] = {0, 0, 0, 0}; int n64 = 0;
    long long sz_big1 = 0, sz_big2 = 0;
    const void *p_big1 = 0, *p_big2 = 0;

    for (int i = 0; i < n_in; i++) {
        long long s = in_sizes[i];
        const void* p = d_in[i];
        if (s > 20000) {
            if (s > sz_big1) { sz_big2 = sz_big1; p_big2 = p_big1; sz_big1 = s; p_big1 = p; }
            else if (s > sz_big2) { sz_big2 = s; p_big2 = p; }
        } else if (s == 16384) W2 = (const float*)p;
        else if (s == 4096) fc1w = (const float*)p;
        else if (s == 1536) W1 = (const float*)p;
        else if (s == 128)  fc2w = (const float*)p;
        else if (s == 2)    fc2b = (const float*)p;
        else if (s == 256) { if (n256 < 3) s256[n256++] = (const float*)p; }
        else if (s == 64)  { if (n64 < 4)  s64g[n64++] = (const float*)p; }
    }
    p_ei = p_big1;
    x    = (const float*)p_big2;

    bool insertion = (n_in >= 2) && ((long long)in_sizes[1] == sz_big1);
    const float* a_s1 = insertion ? s256[0] : s256[1];
    const float* a_d1 = insertion ? s256[1] : s256[0];
    const float* b1   = s256[2];
    const float* a_s2 = insertion ? s64g[0] : s64g[1];
    const float* a_d2 = insertion ? s64g[1] : s64g[0];
    const float* b2   = s64g[2];
    const float* fc1b = s64g[3];
    float* out = (float*)d_out;

    int N  = (int)(sz_big2 / 6);
    int E  = (int)(sz_big1 / 2);
    int nd = out_size / 2;
    if (N > MAXN) N = MAXN;
    if (E > MAXE) E = MAXE;
    int nb = cdiv(N, 1024);            // <= 98

    kz_zero    <<<nb, 1024>>>((const long long*)p_ei, N);
    kc_cvt     <<<cdiv(E, 256), 256>>>(p_ei, E, N);
    kscan      <<<nb, 1024>>>(x, N);
    kscat      <<<cdiv(E, 256), 256>>>(E);
    k1_logits1 <<<cdiv(N, 256), 256>>>(x, W1, a_s1, a_d1, N);
    k4_csr     <<<cdiv(N, 256), 256>>>(N);
    k6_fused   <<<cdiv(N, 32), 256>>>(W1, b1, W2, N);
    k6b_logits2<<<cdiv((long long)N * 32, 256), 256>>>(a_s2, a_d2, N);
    k9_csr     <<<cdiv((long long)N * 32, 256), 256>>>(b2, N);
    k12_mlp    <<<cdiv(nd, 16), 64>>>(fc1w, fc1b, fc2w, fc2b, out, nd);
}